// round 14
// baseline (speedup 1.0000x reference)
#include <cuda_runtime.h>
#include <cuda_fp16.h>
#include <cuda_bf16.h>
#include <cstdint>

#define NN 10000
#define NE 640000
#define DD 128

// ---------------- scratch (static device globals; no allocation) ----------------
__device__ __half g_zh[NN * DD];        // z = (h @ W) * norm_src, fp16 (2.56 MB, L2-resident)
__device__ float  g_norm_src[NN];
__device__ float  g_norm_dst[NN];
__device__ int    g_deg_out_p[NN * 32]; // 128B-strided counters: full LTS partition spread
__device__ int    g_deg_in_p[NN * 32];
__device__ int    g_row_off[NN + 1];    // CSR row offsets by dst
__device__ int    g_csr_src[NE];        // src node per CSR slot
__device__ int    g_src32[NE];          // int32-converted edge lists
__device__ int    g_dst32[NE];
__device__ int    g_rank[NE];           // rank of edge within its dst group (from hist atomic)
__device__ int    g_is64;               // 1 if src/dst buffers are int64, 0 if int32

__device__ __forceinline__ int clampN(int i) {
    return (i < 0) ? 0 : (i >= NN ? NN - 1 : i);
}

// ---------------- setup: probe dtype + zero padded degree arrays (fused) ----------------
// Probe safe under both layouts: reads only first 4096 int32 words (<= NE*4 B).
// int64 data (< 2^31) has every odd word zero; int32 node ids have nonzero odd words.
__global__ void k_probe_init(const int* __restrict__ p32) {
    int i = blockIdx.x * blockDim.x + threadIdx.x;
    if (i < NN * 32) { g_deg_out_p[i] = 0; g_deg_in_p[i] = 0; }
    if (blockIdx.x == 0) {
        __shared__ int any_nz;
        if (threadIdx.x == 0) any_nz = 0;
        __syncthreads();
        for (int w = threadIdx.x * 2 + 1; w < 4096; w += blockDim.x * 2)
            if (p32[w] != 0) any_nz = 1;
        __syncthreads();
        if (threadIdx.x == 0) g_is64 = any_nz ? 0 : 1;
    }
}

// ---------------- fused: int32 conversion + degree histogram + rank (2 edges/thread) ----
// The in-degree atomic's return value IS the edge's rank within its dst group.
__global__ void k_convert_hist(const void* __restrict__ src, const void* __restrict__ dst) {
    int e = (blockIdx.x * blockDim.x + threadIdx.x) * 2;
    if (e >= NE) return;      // NE even
    int s0, s1, d0, d1;
    if (g_is64) {
        longlong2 sv = *(const longlong2*)((const long long*)src + e);  // 16B aligned (e even)
        longlong2 dv = *(const longlong2*)((const long long*)dst + e);
        s0 = clampN((int)sv.x); s1 = clampN((int)sv.y);
        d0 = clampN((int)dv.x); d1 = clampN((int)dv.y);
    } else {
        int2 sv = *(const int2*)((const int*)src + e);
        int2 dv = *(const int2*)((const int*)dst + e);
        s0 = clampN(sv.x); s1 = clampN(sv.y);
        d0 = clampN(dv.x); d1 = clampN(dv.y);
    }
    *(int2*)&g_src32[e] = make_int2(s0, s1);
    *(int2*)&g_dst32[e] = make_int2(d0, d1);
    int r0 = atomicAdd(&g_deg_in_p[d0 * 32], 1);
    int r1 = atomicAdd(&g_deg_in_p[d1 * 32], 1);
    *(int2*)&g_rank[e] = make_int2(r0, r1);
    atomicAdd(&g_deg_out_p[s0 * 32], 1);
    atomicAdd(&g_deg_out_p[s1 * 32], 1);
}

// ---------------- fused norms + exclusive scan (1 block, 1024 threads) ----------------
__global__ void __launch_bounds__(1024) k_norm_scan() {
    int t = threadIdx.x;

    for (int i = t; i < NN; i += 1024) {
        g_norm_src[i] = rsqrtf(fmaxf((float)g_deg_out_p[i * 32], 1.0f));
        g_norm_dst[i] = rsqrtf(fmaxf((float)g_deg_in_p[i * 32],  1.0f));
    }

    const int PER = 10;                 // 1024*10 = 10240 >= NN
    int base = t * PER;
    int loc[PER];
    int run = 0;
    #pragma unroll
    for (int i = 0; i < PER; i++) {
        int idx = base + i;
        int d = (idx < NN) ? g_deg_in_p[idx * 32] : 0;
        loc[i] = run;                   // exclusive within thread
        run += d;
    }

    int lane = t & 31, wid = t >> 5;
    int v = run;
    #pragma unroll
    for (int off = 1; off < 32; off <<= 1) {
        int n = __shfl_up_sync(0xFFFFFFFFu, v, off);
        if (lane >= off) v += n;
    }
    __shared__ int wsum[32];
    if (lane == 31) wsum[wid] = v;
    __syncthreads();
    if (wid == 0) {
        int wv = wsum[lane];
        #pragma unroll
        for (int off = 1; off < 32; off <<= 1) {
            int n = __shfl_up_sync(0xFFFFFFFFu, wv, off);
            if (lane >= off) wv += n;
        }
        wsum[lane] = wv;
    }
    __syncthreads();

    int excl = (v - run) + ((wid > 0) ? wsum[wid - 1] : 0);
    #pragma unroll
    for (int i = 0; i < PER; i++) {
        int idx = base + i;
        if (idx < NN) g_row_off[idx] = excl + loc[i];
    }
    if (t == 1023) g_row_off[NN] = excl + run;
}

// ---------------- scatter: ATOMIC-FREE, 8 edges/thread streaming ----------------
// slot = row_off[dst] + rank (rank < deg_in, row_off exclusive => slot < NE always)
__global__ void k_scatter8() {
    int base = (blockIdx.x * blockDim.x + threadIdx.x) * 8;
    if (base >= NE) return;   // NE divisible by 8
    #pragma unroll
    for (int h = 0; h < 2; h++) {
        int b = base + h * 4;
        int4 d4 = *(const int4*)&g_dst32[b];
        int4 s4 = *(const int4*)&g_src32[b];
        int4 r4 = *(const int4*)&g_rank[b];
        g_csr_src[g_row_off[d4.x] + r4.x] = s4.x;
        g_csr_src[g_row_off[d4.y] + r4.y] = s4.y;
        g_csr_src[g_row_off[d4.z] + r4.z] = s4.z;
        g_csr_src[g_row_off[d4.w] + r4.w] = s4.w;
    }
}

// ---------------- GEMM (tensor core): g_zh = fp16( (h @ W) * norm_src[row] ) ----------------
// Latency-optimized: 32-row tile (grid=313, ~2 blocks/SM), FULL W staged in smem,
// exactly ONE __syncthreads. 256 threads = 8 warps, each owns a 32x16 column slice.
// mma.sync.m16n8k16 f16xf16 + f32 accumulate.
__global__ void __launch_bounds__(256) k_gemm(const float* __restrict__ h,
                                              const float* __restrict__ W) {
    __shared__ __half hA[32][136];    // 8.7 KB  (+8 pad: ldmatrix conflict-free)
    __shared__ __half wB[128][136];   // 34.8 KB

    int tid = threadIdx.x;
    int warp = tid >> 5, lane = tid & 31;
    int blockRow = blockIdx.x * 32;

    // stage A [32 x 128] fp32 -> fp16 (16 independent loads/thread)
    for (int i = tid; i < 32 * 128; i += 256) {
        int r = i >> 7, k = i & 127;
        int grow = blockRow + r;
        hA[r][k] = __float2half_rn((grow < NN) ? h[grow * DD + k] : 0.0f);
    }
    // stage FULL W [128 x 128] fp32 -> fp16 (64 independent loads/thread)
    for (int i = tid; i < 128 * 128; i += 256) {
        int r = i >> 7, c = i & 127;
        wB[r][c] = __float2half_rn(W[r * DD + c]);
    }
    __syncthreads();   // the only barrier

    float acc[2][2][4];
    #pragma unroll
    for (int mt = 0; mt < 2; mt++)
        #pragma unroll
        for (int nt = 0; nt < 2; nt++)
            #pragma unroll
            for (int i = 0; i < 4; i++) acc[mt][nt][i] = 0.0f;

    #pragma unroll
    for (int ks = 0; ks < 8; ks++) {
        // A fragments: 2 m-tiles of m16k16
        unsigned a[2][4];
        #pragma unroll
        for (int mt = 0; mt < 2; mt++) {
            const __half* p = &hA[mt * 16 + (lane & 15)][ks * 16 + (lane >> 4) * 8];
            unsigned ad = (unsigned)__cvta_generic_to_shared(p);
            asm volatile("ldmatrix.sync.aligned.m8n8.x4.shared.b16 {%0,%1,%2,%3},[%4];"
                         : "=r"(a[mt][0]), "=r"(a[mt][1]), "=r"(a[mt][2]), "=r"(a[mt][3])
                         : "r"(ad));
        }
        // B fragments: 2 n-tiles of k16n8 (row-major W -> .trans)
        unsigned b[2][2];
        #pragma unroll
        for (int nt = 0; nt < 2; nt++) {
            const __half* p = &wB[ks * 16 + (lane & 15)][warp * 16 + nt * 8];
            unsigned ad = (unsigned)__cvta_generic_to_shared(p);
            asm volatile("ldmatrix.sync.aligned.m8n8.x2.trans.shared.b16 {%0,%1},[%2];"
                         : "=r"(b[nt][0]), "=r"(b[nt][1]) : "r"(ad));
        }
        #pragma unroll
        for (int mt = 0; mt < 2; mt++)
            #pragma unroll
            for (int nt = 0; nt < 2; nt++) {
                asm volatile(
                    "mma.sync.aligned.m16n8k16.row.col.f32.f16.f16.f32 "
                    "{%0,%1,%2,%3},{%4,%5,%6,%7},{%8,%9},{%0,%1,%2,%3};"
                    : "+f"(acc[mt][nt][0]), "+f"(acc[mt][nt][1]),
                      "+f"(acc[mt][nt][2]), "+f"(acc[mt][nt][3])
                    : "r"(a[mt][0]), "r"(a[mt][1]), "r"(a[mt][2]), "r"(a[mt][3]),
                      "r"(b[nt][0]), "r"(b[nt][1]));
            }
    }

    // epilogue: scale by norm_src, convert fp16, store
    #pragma unroll
    for (int mt = 0; mt < 2; mt++) {
        int r0 = blockRow + mt * 16 + (lane >> 2);
        int r1 = r0 + 8;
        float ns0 = (r0 < NN) ? g_norm_src[r0] : 0.0f;
        float ns1 = (r1 < NN) ? g_norm_src[r1] : 0.0f;
        #pragma unroll
        for (int nt = 0; nt < 2; nt++) {
            int col = warp * 16 + nt * 8 + (lane & 3) * 2;
            if (r0 < NN)
                *(__half2*)&g_zh[r0 * DD + col] =
                    __floats2half2_rn(acc[mt][nt][0] * ns0, acc[mt][nt][1] * ns0);
            if (r1 < NN)
                *(__half2*)&g_zh[r1 * DD + col] =
                    __floats2half2_rn(acc[mt][nt][2] * ns1, acc[mt][nt][3] * ns1);
        }
    }
}

// ---------------- SpMM: out[d] = relu(norm_dst[d] * sum_{e in CSR[d]} z[src_e] + b) ----------------
// One warp per dst node; lane owns 4 cols read as one uint2 (2x half2, 8B) per edge.
// 8x edge unroll, two fp32 accumulator chains -> 8 outstanding 8B gathers per warp.
__global__ void __launch_bounds__(256) k_spmm(const float* __restrict__ bias,
                                              float* __restrict__ out, int do_relu) {
    int w = (blockIdx.x * blockDim.x + threadIdx.x) >> 5;
    int lane = threadIdx.x & 31;
    if (w >= NN) return;

    int beg = g_row_off[w];
    int end = g_row_off[w + 1];

    const uint2* __restrict__ zb = (const uint2*)g_zh;   // 32 uint2 per row
    float4 accA = make_float4(0.f, 0.f, 0.f, 0.f);
    float4 accB = make_float4(0.f, 0.f, 0.f, 0.f);

    int e = beg;
    int n8 = beg + ((end - beg) & ~7);
    for (; e < n8; e += 8) {
        int s0 = g_csr_src[e];
        int s1 = g_csr_src[e + 1];
        int s2 = g_csr_src[e + 2];
        int s3 = g_csr_src[e + 3];
        int s4 = g_csr_src[e + 4];
        int s5 = g_csr_src[e + 5];
        int s6 = g_csr_src[e + 6];
        int s7 = g_csr_src[e + 7];
        uint2 u0 = zb[s0 * 32 + lane];
        uint2 u1 = zb[s1 * 32 + lane];
        uint2 u2 = zb[s2 * 32 + lane];
        uint2 u3 = zb[s3 * 32 + lane];
        uint2 u4 = zb[s4 * 32 + lane];
        uint2 u5 = zb[s5 * 32 + lane];
        uint2 u6 = zb[s6 * 32 + lane];
        uint2 u7 = zb[s7 * 32 + lane];
        #define ACC(ACCV, U) { \
            float2 f0 = __half22float2(*(const __half2*)&(U).x); \
            float2 f1 = __half22float2(*(const __half2*)&(U).y); \
            (ACCV).x += f0.x; (ACCV).y += f0.y; (ACCV).z += f1.x; (ACCV).w += f1.y; }
        ACC(accA, u0) ACC(accA, u1) ACC(accA, u2) ACC(accA, u3)
        ACC(accB, u4) ACC(accB, u5) ACC(accB, u6) ACC(accB, u7)
    }
    for (; e < end; e++) {
        int s = g_csr_src[e];
        uint2 u = zb[s * 32 + lane];
        ACC(accA, u)
    }
    #undef ACC
    accA.x += accB.x; accA.y += accB.y; accA.z += accB.z; accA.w += accB.w;

    float nd = g_norm_dst[w];
    float4 bb = ((const float4*)bias)[lane];
    float4 o;
    o.x = fmaf(accA.x, nd, bb.x);
    o.y = fmaf(accA.y, nd, bb.y);
    o.z = fmaf(accA.z, nd, bb.z);
    o.w = fmaf(accA.w, nd, bb.w);
    if (do_relu) {
        o.x = fmaxf(o.x, 0.f); o.y = fmaxf(o.y, 0.f);
        o.z = fmaxf(o.z, 0.f); o.w = fmaxf(o.w, 0.f);
    }
    ((float4*)out)[w * 32 + lane] = o;
}

// ---------------- launch ----------------
extern "C" void kernel_launch(void* const* d_in, const int* in_sizes, int n_in,
                              void* d_out, int out_size) {
    const float* x   = (const float*)d_in[0];
    const void*  src = d_in[1];
    const void*  dst = d_in[2];
    float* out = (float*)d_out;

    // setup; first gemm kept at launch idx 3 (profiled slot) — it only needs
    // norm_src + x, while scatter8 is independent of it.
    k_probe_init  <<<(NN * 32 + 255) / 256, 256>>>((const int*)src);
    k_convert_hist<<<(NE / 2 + 255) / 256, 256>>>(src, dst);
    k_norm_scan   <<<1, 1024>>>();
    k_gemm        <<<(NN + 31) / 32, 256>>>(x, (const float*)d_in[3]);   // layer 0 gemm
    k_scatter8    <<<(NE / 8 + 255) / 256, 256>>>();

    // layers: output regions of d_out are (h6,h5,h4,h3,h2,h1) -> layer L writes at (5-L)*NN*DD
    const float* cur = x;
    for (int L = 0; L < 6; L++) {
        const float* W = (const float*)d_in[3 + 2 * L];
        const float* b = (const float*)d_in[4 + 2 * L];
        float* hO = out + (size_t)(5 - L) * NN * DD;
        if (L > 0) k_gemm<<<(NN + 31) / 32, 256>>>(cur, W);
        k_spmm<<<(NN * 32 + 255) / 256, 256>>>(b, hO, (L < 5) ? 1 : 0);
        cur = hO;
    }
}

// round 17
// speedup vs baseline: 1.0586x; 1.0586x over previous
#include <cuda_runtime.h>
#include <cuda_fp16.h>
#include <cuda_bf16.h>
#include <cstdint>

#define NN 10000
#define NE 640000
#define DD 128

// ---------------- scratch (static device globals; no allocation) ----------------
__device__ __half g_zh[2 * NN * DD];    // double-buffered z = (h @ W) * norm_src, fp16
__device__ __half g_wh[6 * DD * DD];    // all 6 weight matrices pre-converted to fp16
__device__ float  g_norm_src[NN];
__device__ float  g_norm_dst[NN];
__device__ int    g_deg_out_p[NN * 32]; // 128B-strided counters: full LTS partition spread
__device__ int    g_deg_in_p[NN * 32];
__device__ int    g_row_off[NN + 1];    // CSR row offsets by dst
__device__ int    g_csr_src[NE];        // src node per CSR slot
__device__ int    g_src32[NE];          // int32-converted edge lists
__device__ int    g_dst32[NE];
__device__ int    g_rank[NE];           // rank of edge within its dst group (from hist atomic)
__device__ int    g_is64;               // 1 if src/dst buffers are int64, 0 if int32

__device__ __forceinline__ int clampN(int i) {
    return (i < 0) ? 0 : (i >= NN ? NN - 1 : i);
}

// ---------------- setup: probe dtype + zero degree arrays + W->fp16 (fused) ----------------
__global__ void k_probe_init(const int* __restrict__ p32,
                             const float* __restrict__ w0, const float* __restrict__ w1,
                             const float* __restrict__ w2, const float* __restrict__ w3,
                             const float* __restrict__ w4, const float* __restrict__ w5) {
    int i = blockIdx.x * blockDim.x + threadIdx.x;
    if (i < NN * 32) { g_deg_out_p[i] = 0; g_deg_in_p[i] = 0; }
    if (i < 6 * DD * DD) {
        int l = i >> 14, e = i & 16383;
        const float* wp = (l == 0) ? w0 : (l == 1) ? w1 : (l == 2) ? w2
                         : (l == 3) ? w3 : (l == 4) ? w4 : w5;
        g_wh[i] = __float2half_rn(wp[e]);
    }
    if (blockIdx.x == 0) {
        __shared__ int any_nz;
        if (threadIdx.x == 0) any_nz = 0;
        __syncthreads();
        for (int w = threadIdx.x * 2 + 1; w < 4096; w += blockDim.x * 2)
            if (p32[w] != 0) any_nz = 1;
        __syncthreads();
        if (threadIdx.x == 0) g_is64 = any_nz ? 0 : 1;
    }
}

// ---------------- fused: int32 conversion + degree histogram + rank (2 edges/thread) ----
__global__ void k_convert_hist(const void* __restrict__ src, const void* __restrict__ dst) {
    int e = (blockIdx.x * blockDim.x + threadIdx.x) * 2;
    if (e >= NE) return;      // NE even
    int s0, s1, d0, d1;
    if (g_is64) {
        longlong2 sv = *(const longlong2*)((const long long*)src + e);
        longlong2 dv = *(const longlong2*)((const long long*)dst + e);
        s0 = clampN((int)sv.x); s1 = clampN((int)sv.y);
        d0 = clampN((int)dv.x); d1 = clampN((int)dv.y);
    } else {
        int2 sv = *(const int2*)((const int*)src + e);
        int2 dv = *(const int2*)((const int*)dst + e);
        s0 = clampN(sv.x); s1 = clampN(sv.y);
        d0 = clampN(dv.x); d1 = clampN(dv.y);
    }
    *(int2*)&g_src32[e] = make_int2(s0, s1);
    *(int2*)&g_dst32[e] = make_int2(d0, d1);
    int r0 = atomicAdd(&g_deg_in_p[d0 * 32], 1);
    int r1 = atomicAdd(&g_deg_in_p[d1 * 32], 1);
    *(int2*)&g_rank[e] = make_int2(r0, r1);
    atomicAdd(&g_deg_out_p[s0 * 32], 1);
    atomicAdd(&g_deg_out_p[s1 * 32], 1);
}

// ---------------- fused norms + exclusive scan (1 block, 1024 threads) ----------------
__global__ void __launch_bounds__(1024) k_norm_scan() {
    int t = threadIdx.x;
    for (int i = t; i < NN; i += 1024) {
        g_norm_src[i] = rsqrtf(fmaxf((float)g_deg_out_p[i * 32], 1.0f));
        g_norm_dst[i] = rsqrtf(fmaxf((float)g_deg_in_p[i * 32],  1.0f));
    }
    const int PER = 10;
    int base = t * PER;
    int loc[PER];
    int run = 0;
    #pragma unroll
    for (int i = 0; i < PER; i++) {
        int idx = base + i;
        int d = (idx < NN) ? g_deg_in_p[idx * 32] : 0;
        loc[i] = run;
        run += d;
    }
    int lane = t & 31, wid = t >> 5;
    int v = run;
    #pragma unroll
    for (int off = 1; off < 32; off <<= 1) {
        int n = __shfl_up_sync(0xFFFFFFFFu, v, off);
        if (lane >= off) v += n;
    }
    __shared__ int wsum[32];
    if (lane == 31) wsum[wid] = v;
    __syncthreads();
    if (wid == 0) {
        int wv = wsum[lane];
        #pragma unroll
        for (int off = 1; off < 32; off <<= 1) {
            int n = __shfl_up_sync(0xFFFFFFFFu, wv, off);
            if (lane >= off) wv += n;
        }
        wsum[lane] = wv;
    }
    __syncthreads();
    int excl = (v - run) + ((wid > 0) ? wsum[wid - 1] : 0);
    #pragma unroll
    for (int i = 0; i < PER; i++) {
        int idx = base + i;
        if (idx < NN) g_row_off[idx] = excl + loc[i];
    }
    if (t == 1023) g_row_off[NN] = excl + run;
}

// ---------------- scatter: ATOMIC-FREE, 8 edges/thread streaming ----------------
__global__ void k_scatter8() {
    int base = (blockIdx.x * blockDim.x + threadIdx.x) * 8;
    if (base >= NE) return;
    #pragma unroll
    for (int h = 0; h < 2; h++) {
        int b = base + h * 4;
        int4 d4 = *(const int4*)&g_dst32[b];
        int4 s4 = *(const int4*)&g_src32[b];
        int4 r4 = *(const int4*)&g_rank[b];
        g_csr_src[g_row_off[d4.x] + r4.x] = s4.x;
        g_csr_src[g_row_off[d4.y] + r4.y] = s4.y;
        g_csr_src[g_row_off[d4.z] + r4.z] = s4.z;
        g_csr_src[g_row_off[d4.w] + r4.w] = s4.w;
    }
}

// ---------------- shared mma helpers ----------------
// stage fp16 W [128x128] from g_wh into padded smem (8 x uint4 loads/thread)
__device__ __forceinline__ void stage_w(__half (*wB)[136], const __half* __restrict__ Wh, int tid) {
    #pragma unroll
    for (int it = 0; it < 8; it++) {
        int i = tid + it * 256;               // 0..2047 uint4 = 16384 halves
        int r = i >> 4, c = (i & 15) * 8;
        uint4 v = ((const uint4*)Wh)[i];
        *(uint4*)&wB[r][c] = v;
    }
}

// 32-row x 128-col HMMA tile: z[base..base+32) = (hA @ wB) * norm_src, fp16 out
__device__ __forceinline__ void mma_tile(const __half (*hA)[136], const __half (*wB)[136],
                                         __half* __restrict__ zout, int blockRow,
                                         int warp, int lane) {
    float acc[2][2][4];
    #pragma unroll
    for (int mt = 0; mt < 2; mt++)
        #pragma unroll
        for (int nt = 0; nt < 2; nt++)
            #pragma unroll
            for (int i = 0; i < 4; i++) acc[mt][nt][i] = 0.0f;

    #pragma unroll
    for (int ks = 0; ks < 8; ks++) {
        unsigned a[2][4];
        #pragma unroll
        for (int mt = 0; mt < 2; mt++) {
            const __half* p = &hA[mt * 16 + (lane & 15)][ks * 16 + (lane >> 4) * 8];
            unsigned ad = (unsigned)__cvta_generic_to_shared(p);
            asm volatile("ldmatrix.sync.aligned.m8n8.x4.shared.b16 {%0,%1,%2,%3},[%4];"
                         : "=r"(a[mt][0]), "=r"(a[mt][1]), "=r"(a[mt][2]), "=r"(a[mt][3])
                         : "r"(ad));
        }
        unsigned b[2][2];
        #pragma unroll
        for (int nt = 0; nt < 2; nt++) {
            const __half* p = &wB[ks * 16 + (lane & 15)][warp * 16 + nt * 8];
            unsigned ad = (unsigned)__cvta_generic_to_shared(p);
            asm volatile("ldmatrix.sync.aligned.m8n8.x2.trans.shared.b16 {%0,%1},[%2];"
                         : "=r"(b[nt][0]), "=r"(b[nt][1]) : "r"(ad));
        }
        #pragma unroll
        for (int mt = 0; mt < 2; mt++)
            #pragma unroll
            for (int nt = 0; nt < 2; nt++) {
                asm volatile(
                    "mma.sync.aligned.m16n8k16.row.col.f32.f16.f16.f32 "
                    "{%0,%1,%2,%3},{%4,%5,%6,%7},{%8,%9},{%0,%1,%2,%3};"
                    : "+f"(acc[mt][nt][0]), "+f"(acc[mt][nt][1]),
                      "+f"(acc[mt][nt][2]), "+f"(acc[mt][nt][3])
                    : "r"(a[mt][0]), "r"(a[mt][1]), "r"(a[mt][2]), "r"(a[mt][3]),
                      "r"(b[nt][0]), "r"(b[nt][1]));
            }
    }

    #pragma unroll
    for (int mt = 0; mt < 2; mt++) {
        int r0 = blockRow + mt * 16 + (lane >> 2);
        int r1 = r0 + 8;
        float ns0 = (r0 < NN) ? g_norm_src[r0] : 0.0f;
        float ns1 = (r1 < NN) ? g_norm_src[r1] : 0.0f;
        #pragma unroll
        for (int nt = 0; nt < 2; nt++) {
            int col = warp * 16 + nt * 8 + (lane & 3) * 2;
            if (r0 < NN)
                *(__half2*)&zout[r0 * DD + col] =
                    __floats2half2_rn(acc[mt][nt][0] * ns0, acc[mt][nt][1] * ns0);
            if (r1 < NN)
                *(__half2*)&zout[r1 * DD + col] =
                    __floats2half2_rn(acc[mt][nt][2] * ns1, acc[mt][nt][3] * ns1);
        }
    }
}

// ---------------- standalone GEMM (layer-1 z from fp32 x) ----------------
// widx resolved in DEVICE code (g_wh is a device symbol; its address is not
// valid from host code — that was the R15 bug).
__global__ void __launch_bounds__(256) k_gemm(const float* __restrict__ h,
                                              int widx, int zpar_out) {
    __shared__ __half hA[32][136];
    __shared__ __half wB[128][136];
    int tid = threadIdx.x;
    int warp = tid >> 5, lane = tid & 31;
    int blockRow = blockIdx.x * 32;

    for (int i = tid; i < 32 * 128; i += 256) {
        int r = i >> 7, k = i & 127;
        int grow = blockRow + r;
        hA[r][k] = __float2half_rn((grow < NN) ? h[grow * DD + k] : 0.0f);
    }
    stage_w(wB, g_wh + (size_t)widx * DD * DD, tid);
    __syncthreads();
    mma_tile(hA, wB, g_zh + (size_t)zpar_out * NN * DD, blockRow, warp, lane);
}

// ---------------- FUSED layer: spmm_L (gather z -> h) + gemm_{L+1} (h -> next z) -----
// Block = 256 thr = 8 warps, 32 dst nodes. Phase 1: warp-per-node x4 gather (same
// arithmetic as k_spmm, always relu), writes h rows to out AND fp16 into smem hA.
// Phase 2 (after the single barrier): 32x128 HMMA tile -> z_{L+1}.
__global__ void __launch_bounds__(256) k_layer(const float* __restrict__ bias,
                                               float* __restrict__ out,
                                               int widx, int zpar) {
    __shared__ __half hA[32][136];
    __shared__ __half wB[128][136];
    int tid = threadIdx.x;
    int warp = tid >> 5, lane = tid & 31;
    int blockRow = blockIdx.x * 32;

    stage_w(wB, g_wh + (size_t)widx * DD * DD, tid);   // overlapped with gathers

    const uint2* __restrict__ zb = (const uint2*)(g_zh + (size_t)zpar * NN * DD);
    float4 bb = ((const float4*)bias)[lane];

    #pragma unroll
    for (int i = 0; i < 4; i++) {
        int local = warp + 8 * i;
        int w = blockRow + local;
        if (w < NN) {
            int beg = g_row_off[w];
            int end = g_row_off[w + 1];
            float4 accA = make_float4(0.f, 0.f, 0.f, 0.f);
            float4 accB = make_float4(0.f, 0.f, 0.f, 0.f);
            int e = beg;
            int n8 = beg + ((end - beg) & ~7);
            for (; e < n8; e += 8) {
                int s0 = g_csr_src[e];
                int s1 = g_csr_src[e + 1];
                int s2 = g_csr_src[e + 2];
                int s3 = g_csr_src[e + 3];
                int s4 = g_csr_src[e + 4];
                int s5 = g_csr_src[e + 5];
                int s6 = g_csr_src[e + 6];
                int s7 = g_csr_src[e + 7];
                uint2 u0 = zb[s0 * 32 + lane];
                uint2 u1 = zb[s1 * 32 + lane];
                uint2 u2 = zb[s2 * 32 + lane];
                uint2 u3 = zb[s3 * 32 + lane];
                uint2 u4 = zb[s4 * 32 + lane];
                uint2 u5 = zb[s5 * 32 + lane];
                uint2 u6 = zb[s6 * 32 + lane];
                uint2 u7 = zb[s7 * 32 + lane];
                #define ACC(ACCV, U) { \
                    float2 f0 = __half22float2(*(const __half2*)&(U).x); \
                    float2 f1 = __half22float2(*(const __half2*)&(U).y); \
                    (ACCV).x += f0.x; (ACCV).y += f0.y; (ACCV).z += f1.x; (ACCV).w += f1.y; }
                ACC(accA, u0) ACC(accA, u1) ACC(accA, u2) ACC(accA, u3)
                ACC(accB, u4) ACC(accB, u5) ACC(accB, u6) ACC(accB, u7)
            }
            for (; e < end; e++) {
                int s = g_csr_src[e];
                uint2 u = zb[s * 32 + lane];
                ACC(accA, u)
            }
            #undef ACC
            accA.x += accB.x; accA.y += accB.y; accA.z += accB.z; accA.w += accB.w;

            float nd = g_norm_dst[w];
            float4 o;
            o.x = fmaxf(fmaf(accA.x, nd, bb.x), 0.f);
            o.y = fmaxf(fmaf(accA.y, nd, bb.y), 0.f);
            o.z = fmaxf(fmaf(accA.z, nd, bb.z), 0.f);
            o.w = fmaxf(fmaf(accA.w, nd, bb.w), 0.f);
            ((float4*)out)[w * 32 + lane] = o;

            __half2 p0 = __floats2half2_rn(o.x, o.y);
            __half2 p1 = __floats2half2_rn(o.z, o.w);
            uint2 pk; pk.x = *(unsigned*)&p0; pk.y = *(unsigned*)&p1;
            *(uint2*)&hA[local][lane * 4] = pk;
        } else {
            *(uint2*)&hA[local][lane * 4] = make_uint2(0u, 0u);
        }
    }
    __syncthreads();   // single barrier

    mma_tile(hA, wB, g_zh + (size_t)(1 - zpar) * NN * DD, blockRow, warp, lane);
}

// ---------------- final SpMM (layer 6: no relu, no following gemm) ----------------
__global__ void __launch_bounds__(256) k_spmm(const float* __restrict__ bias,
                                              float* __restrict__ out, int zpar) {
    int w = (blockIdx.x * blockDim.x + threadIdx.x) >> 5;
    int lane = threadIdx.x & 31;
    if (w >= NN) return;
    int beg = g_row_off[w];
    int end = g_row_off[w + 1];
    const uint2* __restrict__ zb = (const uint2*)(g_zh + (size_t)zpar * NN * DD);
    float4 accA = make_float4(0.f, 0.f, 0.f, 0.f);
    float4 accB = make_float4(0.f, 0.f, 0.f, 0.f);
    int e = beg;
    int n8 = beg + ((end - beg) & ~7);
    for (; e < n8; e += 8) {
        int s0 = g_csr_src[e];
        int s1 = g_csr_src[e + 1];
        int s2 = g_csr_src[e + 2];
        int s3 = g_csr_src[e + 3];
        int s4 = g_csr_src[e + 4];
        int s5 = g_csr_src[e + 5];
        int s6 = g_csr_src[e + 6];
        int s7 = g_csr_src[e + 7];
        uint2 u0 = zb[s0 * 32 + lane];
        uint2 u1 = zb[s1 * 32 + lane];
        uint2 u2 = zb[s2 * 32 + lane];
        uint2 u3 = zb[s3 * 32 + lane];
        uint2 u4 = zb[s4 * 32 + lane];
        uint2 u5 = zb[s5 * 32 + lane];
        uint2 u6 = zb[s6 * 32 + lane];
        uint2 u7 = zb[s7 * 32 + lane];
        #define ACC(ACCV, U) { \
            float2 f0 = __half22float2(*(const __half2*)&(U).x); \
            float2 f1 = __half22float2(*(const __half2*)&(U).y); \
            (ACCV).x += f0.x; (ACCV).y += f0.y; (ACCV).z += f1.x; (ACCV).w += f1.y; }
        ACC(accA, u0) ACC(accA, u1) ACC(accA, u2) ACC(accA, u3)
        ACC(accB, u4) ACC(accB, u5) ACC(accB, u6) ACC(accB, u7)
    }
    for (; e < end; e++) {
        int s = g_csr_src[e];
        uint2 u = zb[s * 32 + lane];
        ACC(accA, u)
    }
    #undef ACC
    accA.x += accB.x; accA.y += accB.y; accA.z += accB.z; accA.w += accB.w;
    float nd = g_norm_dst[w];
    float4 bb = ((const float4*)bias)[lane];
    float4 o;
    o.x = fmaf(accA.x, nd, bb.x);
    o.y = fmaf(accA.y, nd, bb.y);
    o.z = fmaf(accA.z, nd, bb.z);
    o.w = fmaf(accA.w, nd, bb.w);
    ((float4*)out)[w * 32 + lane] = o;
}

// ---------------- launch ----------------
extern "C" void kernel_launch(void* const* d_in, const int* in_sizes, int n_in,
                              void* d_out, int out_size) {
    const float* x   = (const float*)d_in[0];
    const void*  src = d_in[1];
    const void*  dst = d_in[2];
    float* out = (float*)d_out;

    // setup (4 launches) + layer-1 gemm at idx 3; first fused layer lands at
    // profiled launch idx 5.
    k_probe_init  <<<(NN * 32 + 255) / 256, 256>>>((const int*)src,
                      (const float*)d_in[3], (const float*)d_in[5],
                      (const float*)d_in[7], (const float*)d_in[9],
                      (const float*)d_in[11], (const float*)d_in[13]);
    k_convert_hist<<<(NE / 2 + 255) / 256, 256>>>(src, dst);
    k_norm_scan   <<<1, 1024>>>();
    k_gemm        <<<(NN + 31) / 32, 256>>>(x, 0, 0);           // z_0 -> buf 0
    k_scatter8    <<<(NE / 8 + 255) / 256, 256>>>();

    // fused layers 0..4: spmm_L (write h_L at (5-L)) + gemm for z_{L+1}
    for (int L = 0; L < 5; L++) {
        const float* b = (const float*)d_in[4 + 2 * L];
        float* hO = out + (size_t)(5 - L) * NN * DD;
        k_layer<<<(NN + 31) / 32, 256>>>(b, hO, L + 1, L & 1);
    }
    // layer 5: plain spmm, no relu, reads z_5 from buf (5&1)=1
    k_spmm<<<(NN * 32 + 255) / 256, 256>>>((const float*)d_in[14], out, 1);
}